// round 3
// baseline (speedup 1.0000x reference)
#include <cuda_runtime.h>
#include <math.h>

static constexpr int F    = 128;
static constexpr int NMAX = 50000;
static constexpr int EMAX = 800000;
static constexpr int BM   = 64;
static constexpr int ASTR = 132;   // padded A smem stride (floats) to avoid bank conflicts

// ---------------- scratch (no allocations allowed) ----------------
__device__ float g_lin[3 * NMAX * F];   // X@W_z, X@W_r, X@W_h
__device__ float g_agg[3 * NMAX * F];   // segment sums, then conv outputs (in place)
__device__ float g_Z  [NMAX * F];
__device__ float g_R  [NMAX * F];
__device__ float g_HR [NMAX * F];
__device__ float g_deg [NMAX];
__device__ float g_dinv[NMAX];
__device__ int   g_src [EMAX];
__device__ int   g_tgt [EMAX];
__device__ float g_coef[EMAX];
__device__ int   g_is64;

// ---------------- edge-index dtype probe + decode ----------------
// If edge_index is int64 (little-endian, values < 2^31), every odd 32-bit
// word of the first row is 0. If int32, odd words are uniform random node ids.
__global__ void probe_kernel(const int* __restrict__ w) {
    __shared__ int nz;
    if (threadIdx.x == 0) nz = 0;
    __syncthreads();
    int local = 0;
    for (int i = threadIdx.x; i < 1024; i += blockDim.x)
        if (w[2 * i + 1] != 0) local = 1;
    if (local) atomicOr(&nz, 1);
    __syncthreads();
    if (threadIdx.x == 0) g_is64 = (nz == 0) ? 1 : 0;
}

__global__ void decode_kernel(const int* __restrict__ w, int E) {
    int e = blockIdx.x * blockDim.x + threadIdx.x;
    if (e >= E) return;
    int s, t;
    if (g_is64) { s = w[2 * e]; t = w[2 * (E + e)]; }
    else        { s = w[e];     t = w[E + e];       }
    g_src[e] = s;
    g_tgt[e] = t;
}

// ---------------- elementwise kernels ----------------
__global__ void init_kernel(int n) {
    int i = blockIdx.x * blockDim.x + threadIdx.x;
    int tot4 = 3 * n * (F / 4);
    if (i < tot4) ((float4*)g_agg)[i] = make_float4(0.f, 0.f, 0.f, 0.f);
    if (i < n) g_deg[i] = 1.0f;   // self-loop weight
}

__global__ void deg_kernel(const float* __restrict__ ew, int E) {
    int e = blockIdx.x * blockDim.x + threadIdx.x;
    if (e >= E) return;
    atomicAdd(&g_deg[g_tgt[e]], ew[e]);
}

__global__ void dinv_kernel(int n) {
    int i = blockIdx.x * blockDim.x + threadIdx.x;
    if (i < n) g_dinv[i] = rsqrtf(g_deg[i]);
}

__global__ void coef_kernel(const float* __restrict__ ew, int E) {
    int e = blockIdx.x * blockDim.x + threadIdx.x;
    if (e >= E) return;
    g_coef[e] = g_dinv[g_src[e]] * ew[e] * g_dinv[g_tgt[e]];
}

// one warp per edge; 3 channels share index loads + coefficient
__global__ void scatter_kernel(int E, int n) {
    int gw   = (blockIdx.x * blockDim.x + threadIdx.x) >> 5;
    int lane = threadIdx.x & 31;
    if (gw >= E) return;
    int s   = g_src[gw];
    int t   = g_tgt[gw];
    float c = g_coef[gw];
    int nf = n * F;
#pragma unroll
    for (int ch = 0; ch < 3; ch++) {
        const float* lp = g_lin + ch * nf + s * F;
        float*       ap = g_agg + ch * nf + t * F;
#pragma unroll
        for (int j = 0; j < 4; j++) {
            int o = lane + j * 32;                 // coalesced 128B per RED
            atomicAdd(ap + o, c * __ldg(lp + o));
        }
    }
}

// conv = agg + lin * dinv^2 + b   (in place into g_agg)
__global__ void combine_kernel(const float* __restrict__ bz,
                               const float* __restrict__ br,
                               const float* __restrict__ bh, int n) {
    int i4 = blockIdx.x * blockDim.x + threadIdx.x;
    int nf4 = n * (F / 4);
    int tot4 = 3 * nf4;
    if (i4 >= tot4) return;
    int ch   = i4 / nf4;
    int rem  = i4 - ch * nf4;
    int node = rem / (F / 4);
    int f4   = rem & (F / 4 - 1);
    const float* bp = (ch == 0) ? bz : (ch == 1) ? br : bh;
    float d  = g_dinv[node];
    float d2 = d * d;
    float4 l = ((const float4*)g_lin)[i4];
    float4 a = ((float4*)g_agg)[i4];
    float4 b = ((const float4*)bp)[f4];
    a.x += l.x * d2 + b.x;
    a.y += l.y * d2 + b.y;
    a.z += l.z * d2 + b.z;
    a.w += l.w * d2 + b.w;
    ((float4*)g_agg)[i4] = a;
}

__global__ void hr_kernel(const float* __restrict__ H, int n) {
    int i = blockIdx.x * blockDim.x + threadIdx.x;
    if (i >= n * (F / 4)) return;
    float4 h = ((const float4*)H)[i];
    float4 r = ((const float4*)g_R)[i];
    ((float4*)g_HR)[i] = make_float4(h.x * r.x, h.y * r.y, h.z * r.z, h.w * r.w);
}

// ---------------- GEMM ----------------
// C[M,128] = A[M, NCHUNK*128] @ B[NCHUNK*128, 128], A is [A0 | A1] chunks.
// MODE 0: out = acc
// MODE 1: out = sigmoid(acc + bias)
// MODE 2: out = Z*H + (1-Z)*tanh(acc + bias)   (fused final epilogue)
template <int MODE, int NCHUNK>
__global__ void gemm_kernel(const float* __restrict__ A0,
                            const float* __restrict__ A1,
                            const float* __restrict__ B,
                            const float* __restrict__ bias,
                            const float* __restrict__ Zb,
                            const float* __restrict__ Hb,
                            float* __restrict__ out, int M) {
    extern __shared__ float sm[];
    float* As = sm;                 // BM * ASTR
    float* Bs = sm + BM * ASTR;     // 128 * 128
    int tid  = threadIdx.x;         // 256 threads
    int row0 = blockIdx.x * BM;
    int ty = tid >> 4, tx = tid & 15;
    int r0 = ty * 4, c0 = tx * 8;
    int remRows = M - row0;

    float acc[4][8];
#pragma unroll
    for (int i = 0; i < 4; i++)
#pragma unroll
        for (int j = 0; j < 8; j++) acc[i][j] = 0.f;

    for (int kc = 0; kc < NCHUNK; kc++) {
        const float* A  = (NCHUNK == 1 || kc == 0) ? A0 : A1;
        const float* Ab = A + (size_t)row0 * F;
        // stage A tile (guard rows, pad stride)
        for (int i = tid; i < BM * (F / 4); i += 256) {
            int r  = i >> 5;
            int c4 = i & 31;
            float4 v = make_float4(0.f, 0.f, 0.f, 0.f);
            if (r < remRows) v = ((const float4*)(Ab + (size_t)r * F))[c4];
            *(float4*)(As + r * ASTR + c4 * 4) = v;
        }
        // stage B tile (full 128x128 weight chunk)
        const float4* bsrc = (const float4*)(B + kc * F * F);
#pragma unroll
        for (int i = 0; i < 16; i++)
            ((float4*)Bs)[tid + i * 256] = bsrc[tid + i * 256];
        __syncthreads();

#pragma unroll 8
        for (int k = 0; k < F; k++) {
            float4 bA = *(const float4*)(Bs + k * F + c0);
            float4 bB = *(const float4*)(Bs + k * F + c0 + 4);
            float av[4];
            av[0] = As[(r0 + 0) * ASTR + k];
            av[1] = As[(r0 + 1) * ASTR + k];
            av[2] = As[(r0 + 2) * ASTR + k];
            av[3] = As[(r0 + 3) * ASTR + k];
#pragma unroll
            for (int i = 0; i < 4; i++) {
                acc[i][0] += av[i] * bA.x;
                acc[i][1] += av[i] * bA.y;
                acc[i][2] += av[i] * bA.z;
                acc[i][3] += av[i] * bA.w;
                acc[i][4] += av[i] * bB.x;
                acc[i][5] += av[i] * bB.y;
                acc[i][6] += av[i] * bB.z;
                acc[i][7] += av[i] * bB.w;
            }
        }
        __syncthreads();
    }

#pragma unroll
    for (int i = 0; i < 4; i++) {
        int gr = row0 + r0 + i;
        if (gr >= M) break;
        size_t base = (size_t)gr * F + c0;
        if (MODE == 0) {
            *(float4*)(out + base)     = make_float4(acc[i][0], acc[i][1], acc[i][2], acc[i][3]);
            *(float4*)(out + base + 4) = make_float4(acc[i][4], acc[i][5], acc[i][6], acc[i][7]);
        } else if (MODE == 1) {
#pragma unroll
            for (int j = 0; j < 8; j++) {
                float v = acc[i][j] + bias[c0 + j];
                out[base + j] = 1.f / (1.f + __expf(-v));
            }
        } else {
#pragma unroll
            for (int j = 0; j < 8; j++) {
                float v = tanhf(acc[i][j] + bias[c0 + j]);
                float z = Zb[base + j];
                float h = Hb[base + j];
                out[base + j] = z * h + (1.f - z) * v;
            }
        }
    }
}

// ---------------- launch ----------------
extern "C" void kernel_launch(void* const* d_in, const int* in_sizes, int n_in,
                              void* d_out, int out_size) {
    const float* X    = (const float*)d_in[0];
    const int*   eiw  = (const int*)d_in[1];    // edge_index, dtype probed at runtime
    const float* ew   = (const float*)d_in[2];
    const float* H    = (const float*)d_in[3];
    const float* W_z  = (const float*)d_in[4];
    const float* b_z  = (const float*)d_in[5];
    const float* W_r  = (const float*)d_in[6];
    const float* b_r  = (const float*)d_in[7];
    const float* W_h  = (const float*)d_in[8];
    const float* b_h  = (const float*)d_in[9];
    const float* Wl_z = (const float*)d_in[10];
    const float* bl_z = (const float*)d_in[11];
    const float* Wl_r = (const float*)d_in[12];
    const float* bl_r = (const float*)d_in[13];
    const float* Wl_h = (const float*)d_in[14];
    const float* bl_h = (const float*)d_in[15];
    float*       out  = (float*)d_out;

    int n = in_sizes[0] / F;   // 50000
    int E = in_sizes[2];       // 800000 (edge_weight count — dtype-independent)
    int nf = n * F;

    float *lin, *agg, *Zp, *Rp, *HRp;
    cudaGetSymbolAddress((void**)&lin, g_lin);
    cudaGetSymbolAddress((void**)&agg, g_agg);
    cudaGetSymbolAddress((void**)&Zp,  g_Z);
    cudaGetSymbolAddress((void**)&Rp,  g_R);
    cudaGetSymbolAddress((void**)&HRp, g_HR);

    const int smem = (BM * ASTR + F * F) * (int)sizeof(float);
    cudaFuncSetAttribute(gemm_kernel<0, 1>, cudaFuncAttributeMaxDynamicSharedMemorySize, smem);
    cudaFuncSetAttribute(gemm_kernel<1, 2>, cudaFuncAttributeMaxDynamicSharedMemorySize, smem);
    cudaFuncSetAttribute(gemm_kernel<2, 2>, cudaFuncAttributeMaxDynamicSharedMemorySize, smem);

    probe_kernel<<<1, 256>>>(eiw);
    decode_kernel<<<(E + 255) / 256, 256>>>(eiw, E);

    init_kernel<<<(3 * nf / 4 + 255) / 256, 256>>>(n);
    deg_kernel<<<(E + 255) / 256, 256>>>(ew, E);
    dinv_kernel<<<(n + 255) / 256, 256>>>(n);
    coef_kernel<<<(E + 255) / 256, 256>>>(ew, E);

    int gblocks = (n + BM - 1) / BM;
    gemm_kernel<0, 1><<<gblocks, 256, smem>>>(X, nullptr, W_z, nullptr, nullptr, nullptr, lin,          n);
    gemm_kernel<0, 1><<<gblocks, 256, smem>>>(X, nullptr, W_r, nullptr, nullptr, nullptr, lin + nf,     n);
    gemm_kernel<0, 1><<<gblocks, 256, smem>>>(X, nullptr, W_h, nullptr, nullptr, nullptr, lin + 2 * nf, n);

    scatter_kernel<<<(E * 32 + 255) / 256, 256>>>(E, n);
    combine_kernel<<<(3 * nf / 4 + 255) / 256, 256>>>(b_z, b_r, b_h, n);

    gemm_kernel<1, 2><<<gblocks, 256, smem>>>(agg,          H,   Wl_z, bl_z, nullptr, nullptr, Zp,  n);
    gemm_kernel<1, 2><<<gblocks, 256, smem>>>(agg + nf,     H,   Wl_r, bl_r, nullptr, nullptr, Rp,  n);
    hr_kernel<<<(nf / 4 + 255) / 256, 256>>>(H, n);
    gemm_kernel<2, 2><<<gblocks, 256, smem>>>(agg + 2 * nf, HRp, Wl_h, bl_h, Zp,      H,       out, n);
}

// round 4
// speedup vs baseline: 1.6464x; 1.6464x over previous
#include <cuda_runtime.h>
#include <math.h>

static constexpr int F    = 128;
static constexpr int NMAX = 50000;
static constexpr int EMAX = 800000;
static constexpr int BM   = 64;
static constexpr int ASTR = 132;   // padded A smem stride (floats) to avoid bank conflicts

// ---------------- scratch (no allocations allowed) ----------------
__device__ float g_xagg[NMAX * F];      // segsum(x[src]*coef) + x*dinv^2
__device__ float g_Z   [NMAX * F];
__device__ float g_HR  [NMAX * F];
__device__ float g_Aw  [3 * F * F];     // W_c @ Wl_c_top for c in {z,r,h}
__device__ float g_cb  [3 * F];         // b_c @ Wl_c_top + bl_c
__device__ float g_deg [NMAX];
__device__ float g_dinv[NMAX];
__device__ int   g_src [EMAX];
__device__ int   g_tgt [EMAX];
__device__ float g_coef[EMAX];
__device__ int   g_is64;

// ---------------- edge-index dtype probe + decode ----------------
// int64 little-endian with values < 2^31 -> every odd 32-bit word of row 0 is 0.
__global__ void probe_kernel(const int* __restrict__ w) {
    __shared__ int nz;
    if (threadIdx.x == 0) nz = 0;
    __syncthreads();
    int local = 0;
    for (int i = threadIdx.x; i < 1024; i += blockDim.x)
        if (w[2 * i + 1] != 0) local = 1;
    if (local) atomicOr(&nz, 1);
    __syncthreads();
    if (threadIdx.x == 0) g_is64 = (nz == 0) ? 1 : 0;
}

__global__ void decode_kernel(const int* __restrict__ w, int E) {
    int e = blockIdx.x * blockDim.x + threadIdx.x;
    if (e >= E) return;
    int s, t;
    if (g_is64) { s = w[2 * e]; t = w[2 * (E + e)]; }
    else        { s = w[e];     t = w[E + e];       }
    g_src[e] = s;
    g_tgt[e] = t;
}

// ---------------- graph prep ----------------
__global__ void initdeg_kernel(int n) {
    int i = blockIdx.x * blockDim.x + threadIdx.x;
    if (i < n) g_deg[i] = 1.0f;   // self-loop
}

__global__ void deg_kernel(const float* __restrict__ ew, int E) {
    int e = blockIdx.x * blockDim.x + threadIdx.x;
    if (e >= E) return;
    atomicAdd(&g_deg[g_tgt[e]], ew[e]);
}

__global__ void dinv_kernel(int n) {
    int i = blockIdx.x * blockDim.x + threadIdx.x;
    if (i < n) g_dinv[i] = rsqrtf(g_deg[i]);
}

__global__ void coef_kernel(const float* __restrict__ ew, int E) {
    int e = blockIdx.x * blockDim.x + threadIdx.x;
    if (e >= E) return;
    g_coef[e] = g_dinv[g_src[e]] * ew[e] * g_dinv[g_tgt[e]];
}

// xagg = x * dinv^2  (self-loop term), before edge scatter adds into it
__global__ void xinit_kernel(const float* __restrict__ X, int n) {
    int i4 = blockIdx.x * blockDim.x + threadIdx.x;
    if (i4 >= n * (F / 4)) return;
    int node = i4 >> 5;
    float d = g_dinv[node];
    float d2 = d * d;
    float4 v = ((const float4*)X)[i4];
    ((float4*)g_xagg)[i4] = make_float4(v.x * d2, v.y * d2, v.z * d2, v.w * d2);
}

// one warp per edge, single (pre-GEMM) feature channel
__global__ void scatter_kernel(const float* __restrict__ X, int E) {
    int gw   = (blockIdx.x * blockDim.x + threadIdx.x) >> 5;
    int lane = threadIdx.x & 31;
    if (gw >= E) return;
    int s   = g_src[gw];
    int t   = g_tgt[gw];
    float c = g_coef[gw];
    const float* xp = X + (size_t)s * F;
    float*       ap = g_xagg + (size_t)t * F;
#pragma unroll
    for (int j = 0; j < 4; j++) {
        int o = lane + j * 32;                 // coalesced 128B per RED
        atomicAdd(ap + o, c * __ldg(xp + o));
    }
}

// combined bias: cb[ch][j] = sum_k b[ch][k] * Wl[ch][k][j] + bl[ch][j]
__global__ void biasprep_kernel(const float* __restrict__ bz, const float* __restrict__ Wlz, const float* __restrict__ blz,
                                const float* __restrict__ br, const float* __restrict__ Wlr, const float* __restrict__ blr,
                                const float* __restrict__ bh, const float* __restrict__ Wlh, const float* __restrict__ blh) {
    int t = threadIdx.x;               // 384 threads: ch = t/128, j = t%128
    int ch = t >> 7, j = t & 127;
    const float* b  = (ch == 0) ? bz  : (ch == 1) ? br  : bh;
    const float* Wl = (ch == 0) ? Wlz : (ch == 1) ? Wlr : Wlh;
    const float* bl = (ch == 0) ? blz : (ch == 1) ? blr : blh;
    float acc = bl[j];
    for (int k = 0; k < F; k++) acc += b[k] * Wl[k * F + j];
    g_cb[ch * F + j] = acc;
}

// ---------------- GEMM ----------------
// C[M,128] = sum_kc A_kc[M,128] @ B_kc[128,128]  (+ epilogue)
// MODE 0: out = acc                               (weight prep)
// MODE 1: out = sigmoid(acc + bias)               (Z)
// MODE 3: out = H * sigmoid(acc + bias)           (HR, fused R)
// MODE 2: out = Z*H + (1-Z)*tanh(acc + bias)      (final)
template <int MODE, int NCHUNK>
__global__ void gemm_kernel(const float* __restrict__ A0,
                            const float* __restrict__ A1,
                            const float* __restrict__ B0,
                            const float* __restrict__ B1,
                            const float* __restrict__ bias,
                            const float* __restrict__ Zb,
                            const float* __restrict__ Hb,
                            float* __restrict__ out, int M) {
    extern __shared__ float sm[];
    float* As = sm;                 // BM * ASTR
    float* Bs = sm + BM * ASTR;     // 128 * 128
    int tid  = threadIdx.x;         // 256 threads
    int row0 = blockIdx.x * BM;
    int ty = tid >> 4, tx = tid & 15;
    int r0 = ty * 4, c0 = tx * 8;
    int remRows = M - row0;

    float acc[4][8];
#pragma unroll
    for (int i = 0; i < 4; i++)
#pragma unroll
        for (int j = 0; j < 8; j++) acc[i][j] = 0.f;

#pragma unroll
    for (int kc = 0; kc < NCHUNK; kc++) {
        const float* A  = (kc == 0) ? A0 : A1;
        const float* Bc = (kc == 0) ? B0 : B1;
        const float* Ab = A + (size_t)row0 * F;
        for (int i = tid; i < BM * (F / 4); i += 256) {
            int r  = i >> 5;
            int c4 = i & 31;
            float4 v = make_float4(0.f, 0.f, 0.f, 0.f);
            if (r < remRows) v = ((const float4*)(Ab + (size_t)r * F))[c4];
            *(float4*)(As + r * ASTR + c4 * 4) = v;
        }
        const float4* bsrc = (const float4*)Bc;
#pragma unroll
        for (int i = 0; i < 16; i++)
            ((float4*)Bs)[tid + i * 256] = bsrc[tid + i * 256];
        __syncthreads();

#pragma unroll 8
        for (int k = 0; k < F; k++) {
            float4 bA = *(const float4*)(Bs + k * F + c0);
            float4 bB = *(const float4*)(Bs + k * F + c0 + 4);
            float av[4];
            av[0] = As[(r0 + 0) * ASTR + k];
            av[1] = As[(r0 + 1) * ASTR + k];
            av[2] = As[(r0 + 2) * ASTR + k];
            av[3] = As[(r0 + 3) * ASTR + k];
#pragma unroll
            for (int i = 0; i < 4; i++) {
                acc[i][0] += av[i] * bA.x;
                acc[i][1] += av[i] * bA.y;
                acc[i][2] += av[i] * bA.z;
                acc[i][3] += av[i] * bA.w;
                acc[i][4] += av[i] * bB.x;
                acc[i][5] += av[i] * bB.y;
                acc[i][6] += av[i] * bB.z;
                acc[i][7] += av[i] * bB.w;
            }
        }
        __syncthreads();
    }

#pragma unroll
    for (int i = 0; i < 4; i++) {
        int gr = row0 + r0 + i;
        if (gr >= M) break;
        size_t base = (size_t)gr * F + c0;
        if (MODE == 0) {
            *(float4*)(out + base)     = make_float4(acc[i][0], acc[i][1], acc[i][2], acc[i][3]);
            *(float4*)(out + base + 4) = make_float4(acc[i][4], acc[i][5], acc[i][6], acc[i][7]);
        } else if (MODE == 1) {
#pragma unroll
            for (int j = 0; j < 8; j++) {
                float v = acc[i][j] + bias[c0 + j];
                out[base + j] = 1.f / (1.f + __expf(-v));
            }
        } else if (MODE == 3) {
#pragma unroll
            for (int j = 0; j < 8; j++) {
                float v = acc[i][j] + bias[c0 + j];
                float r = 1.f / (1.f + __expf(-v));
                out[base + j] = Hb[base + j] * r;
            }
        } else {
#pragma unroll
            for (int j = 0; j < 8; j++) {
                float v = tanhf(acc[i][j] + bias[c0 + j]);
                float z = Zb[base + j];
                float h = Hb[base + j];
                out[base + j] = z * h + (1.f - z) * v;
            }
        }
    }
}

// ---------------- launch ----------------
extern "C" void kernel_launch(void* const* d_in, const int* in_sizes, int n_in,
                              void* d_out, int out_size) {
    const float* X    = (const float*)d_in[0];
    const int*   eiw  = (const int*)d_in[1];    // edge_index, dtype probed at runtime
    const float* ew   = (const float*)d_in[2];
    const float* H    = (const float*)d_in[3];
    const float* W_z  = (const float*)d_in[4];
    const float* b_z  = (const float*)d_in[5];
    const float* W_r  = (const float*)d_in[6];
    const float* b_r  = (const float*)d_in[7];
    const float* W_h  = (const float*)d_in[8];
    const float* b_h  = (const float*)d_in[9];
    const float* Wl_z = (const float*)d_in[10];
    const float* bl_z = (const float*)d_in[11];
    const float* Wl_r = (const float*)d_in[12];
    const float* bl_r = (const float*)d_in[13];
    const float* Wl_h = (const float*)d_in[14];
    const float* bl_h = (const float*)d_in[15];
    float*       out  = (float*)d_out;

    int n = in_sizes[0] / F;   // 50000
    int E = in_sizes[2];       // 800000
    int nf = n * F;

    float *xagg, *Zp, *HRp, *Aw, *cb;
    cudaGetSymbolAddress((void**)&xagg, g_xagg);
    cudaGetSymbolAddress((void**)&Zp,   g_Z);
    cudaGetSymbolAddress((void**)&HRp,  g_HR);
    cudaGetSymbolAddress((void**)&Aw,   g_Aw);
    cudaGetSymbolAddress((void**)&cb,   g_cb);

    const int smem = (BM * ASTR + F * F) * (int)sizeof(float);
    cudaFuncSetAttribute(gemm_kernel<0, 1>, cudaFuncAttributeMaxDynamicSharedMemorySize, smem);
    cudaFuncSetAttribute(gemm_kernel<1, 2>, cudaFuncAttributeMaxDynamicSharedMemorySize, smem);
    cudaFuncSetAttribute(gemm_kernel<2, 2>, cudaFuncAttributeMaxDynamicSharedMemorySize, smem);
    cudaFuncSetAttribute(gemm_kernel<3, 2>, cudaFuncAttributeMaxDynamicSharedMemorySize, smem);

    // edge decode + graph coefficients
    probe_kernel<<<1, 256>>>(eiw);
    decode_kernel<<<(E + 255) / 256, 256>>>(eiw, E);
    initdeg_kernel<<<(n + 255) / 256, 256>>>(n);
    deg_kernel<<<(E + 255) / 256, 256>>>(ew, E);
    dinv_kernel<<<(n + 255) / 256, 256>>>(n);
    coef_kernel<<<(E + 255) / 256, 256>>>(ew, E);

    // weight prep: Aw[ch] = W_ch @ Wl_ch_top ; cb[ch] = b_ch @ Wl_ch_top + bl_ch
    const int pb = (F + BM - 1) / BM;  // 2 blocks
    gemm_kernel<0, 1><<<pb, 256, smem>>>(W_z, nullptr, Wl_z, nullptr, nullptr, nullptr, nullptr, Aw,         F);
    gemm_kernel<0, 1><<<pb, 256, smem>>>(W_r, nullptr, Wl_r, nullptr, nullptr, nullptr, nullptr, Aw + F * F, F);
    gemm_kernel<0, 1><<<pb, 256, smem>>>(W_h, nullptr, Wl_h, nullptr, nullptr, nullptr, nullptr, Aw + 2*F*F, F);
    biasprep_kernel<<<1, 384>>>(b_z, Wl_z, bl_z, b_r, Wl_r, bl_r, b_h, Wl_h, bl_h);

    // aggregate X over the graph (single channel)
    xinit_kernel<<<(nf / 4 + 255) / 256, 256>>>(X, n);
    scatter_kernel<<<(E * 32 + 255) / 256, 256>>>(X, E);

    // fused linear stages
    int gblocks = (n + BM - 1) / BM;
    // Z  = sigmoid(xagg@Az + H@Wl_z_bot + cz)
    gemm_kernel<1, 2><<<gblocks, 256, smem>>>(xagg, H,   Aw,         Wl_z + F * F, cb,         nullptr, nullptr, Zp,  n);
    // HR = H * sigmoid(xagg@Ar + H@Wl_r_bot + cr)
    gemm_kernel<3, 2><<<gblocks, 256, smem>>>(xagg, H,   Aw + F * F, Wl_r + F * F, cb + F,     nullptr, H,       HRp, n);
    // out = Z*H + (1-Z)*tanh(xagg@Ah + HR@Wl_h_bot + ch)
    gemm_kernel<2, 2><<<gblocks, 256, smem>>>(xagg, HRp, Aw + 2*F*F, Wl_h + F * F, cb + 2 * F, Zp,      H,       out, n);
}

// round 6
// speedup vs baseline: 2.8620x; 1.7384x over previous
#include <cuda_runtime.h>
#include <cuda_bf16.h>
#include <math.h>
#include <stdint.h>

static constexpr int F    = 128;
static constexpr int NMAX = 50000;
static constexpr int EMAX = 800000;
static constexpr int BM   = 64;
static constexpr int ASTR = 132;

// ---- tc_gemm smem layout (bytes) ----
// Bs hi [128][264] bf16 = 67584 ; Bs lo same ; As hi [128][72] bf16 = 18432 ; As lo same
static constexpr int SM_BH = 0;
static constexpr int SM_BL = 67584;
static constexpr int SM_AH = 135168;
static constexpr int SM_AL = 153600;
static constexpr int TC_SMEM = 172032;
static constexpr int BSTR = 264;   // bf16 elements per B smem row (256 + 8 pad)
static constexpr int ASTRB = 72;   // bf16 elements per A smem row (64 + 8 pad)

// ---------------- scratch (no allocations allowed) ----------------
__device__ float g_xagg[NMAX * F];
__device__ float g_Z   [NMAX * F];
__device__ float g_HR  [NMAX * F];
__device__ float g_Aw  [3 * F * F];            // W_c @ Wl_c_top
__device__ float g_cb  [3 * F];                // b_c @ Wl_c_top + bl_c
__device__ __nv_bfloat16 g_Bh[3 * F * 256];    // B images [ch][n=128][k=256] (hi)
__device__ __nv_bfloat16 g_Bl[3 * F * 256];    // (lo)
__device__ float g_deg [NMAX];
__device__ float g_dinv[NMAX];
__device__ int   g_src [EMAX];
__device__ int   g_tgt [EMAX];
__device__ float g_coef[EMAX];
__device__ int   g_is64;

// ---------------- helpers ----------------
__device__ __forceinline__ uint32_t smem_u32(const void* p) {
    uint32_t a;
    asm("{ .reg .u64 t; cvta.to.shared.u64 t, %1; cvt.u32.u64 %0, t; }" : "=r"(a) : "l"(p));
    return a;
}
__device__ __forceinline__ void ldm_x4(uint32_t* r, uint32_t addr) {
    asm volatile("ldmatrix.sync.aligned.m8n8.x4.shared.b16 {%0,%1,%2,%3}, [%4];"
                 : "=r"(r[0]), "=r"(r[1]), "=r"(r[2]), "=r"(r[3]) : "r"(addr));
}
__device__ __forceinline__ void mma_bf16(float* c, const uint32_t* a, uint32_t b0, uint32_t b1) {
    asm volatile("mma.sync.aligned.m16n8k16.row.col.f32.bf16.bf16.f32 "
                 "{%0,%1,%2,%3}, {%4,%5,%6,%7}, {%8,%9}, {%0,%1,%2,%3};"
                 : "+f"(c[0]), "+f"(c[1]), "+f"(c[2]), "+f"(c[3])
                 : "r"(a[0]), "r"(a[1]), "r"(a[2]), "r"(a[3]), "r"(b0), "r"(b1));
}
__device__ __forceinline__ uint32_t pack_bf2(float a, float b) {
    __nv_bfloat16 ha = __float2bfloat16(a), hb = __float2bfloat16(b);
    return ((uint32_t)__bfloat16_as_ushort(hb) << 16) | (uint32_t)__bfloat16_as_ushort(ha);
}

// ---------------- edge-index dtype probe + decode ----------------
__global__ void probe_kernel(const int* __restrict__ w) {
    __shared__ int nz;
    if (threadIdx.x == 0) nz = 0;
    __syncthreads();
    int local = 0;
    for (int i = threadIdx.x; i < 1024; i += blockDim.x)
        if (w[2 * i + 1] != 0) local = 1;
    if (local) atomicOr(&nz, 1);
    __syncthreads();
    if (threadIdx.x == 0) g_is64 = (nz == 0) ? 1 : 0;
}
__global__ void decode_kernel(const int* __restrict__ w, int E) {
    int e = blockIdx.x * blockDim.x + threadIdx.x;
    if (e >= E) return;
    int s, t;
    if (g_is64) { s = w[2 * e]; t = w[2 * (E + e)]; }
    else        { s = w[e];     t = w[E + e];       }
    g_src[e] = s;
    g_tgt[e] = t;
}

// ---------------- graph prep ----------------
__global__ void initdeg_kernel(int n) {
    int i = blockIdx.x * blockDim.x + threadIdx.x;
    if (i < n) g_deg[i] = 1.0f;
}
__global__ void deg_kernel(const float* __restrict__ ew, int E) {
    int e = blockIdx.x * blockDim.x + threadIdx.x;
    if (e >= E) return;
    atomicAdd(&g_deg[g_tgt[e]], ew[e]);
}
__global__ void dinv_kernel(int n) {
    int i = blockIdx.x * blockDim.x + threadIdx.x;
    if (i < n) g_dinv[i] = rsqrtf(g_deg[i]);
}
__global__ void coef_kernel(const float* __restrict__ ew, int E) {
    int e = blockIdx.x * blockDim.x + threadIdx.x;
    if (e >= E) return;
    g_coef[e] = g_dinv[g_src[e]] * ew[e] * g_dinv[g_tgt[e]];
}
__global__ void xinit_kernel(const float* __restrict__ X, int n) {
    int i4 = blockIdx.x * blockDim.x + threadIdx.x;
    if (i4 >= n * (F / 4)) return;
    int node = i4 >> 5;
    float d = g_dinv[node];
    float d2 = d * d;
    float4 v = ((const float4*)X)[i4];
    ((float4*)g_xagg)[i4] = make_float4(v.x * d2, v.y * d2, v.z * d2, v.w * d2);
}
__global__ void scatter_kernel(const float* __restrict__ X, int E) {
    int gw   = (blockIdx.x * blockDim.x + threadIdx.x) >> 5;
    int lane = threadIdx.x & 31;
    if (gw >= E) return;
    int s   = g_src[gw];
    int t   = g_tgt[gw];
    float c = g_coef[gw];
    const float* xp = X + (size_t)s * F;
    float*       ap = g_xagg + (size_t)t * F;
#pragma unroll
    for (int j = 0; j < 4; j++) {
        int o = lane + j * 32;
        atomicAdd(ap + o, c * __ldg(xp + o));
    }
}
__global__ void biasprep_kernel(const float* __restrict__ bz, const float* __restrict__ Wlz, const float* __restrict__ blz,
                                const float* __restrict__ br, const float* __restrict__ Wlr, const float* __restrict__ blr,
                                const float* __restrict__ bh, const float* __restrict__ Wlh, const float* __restrict__ blh) {
    int t = threadIdx.x;               // 384 threads
    int ch = t >> 7, j = t & 127;
    const float* b  = (ch == 0) ? bz  : (ch == 1) ? br  : bh;
    const float* Wl = (ch == 0) ? Wlz : (ch == 1) ? Wlr : Wlh;
    const float* bl = (ch == 0) ? blz : (ch == 1) ? blr : blh;
    float acc = bl[j];
    for (int k = 0; k < F; k++) acc += b[k] * Wl[k * F + j];
    g_cb[ch * F + j] = acc;
}

// build B images [ch][n][k] = Wcomb[k][n] in bf16 hi/lo
// grid 768 blocks (ch*256 + k), 128 threads = n
__global__ void bprep_kernel(const float* __restrict__ Wlz,
                             const float* __restrict__ Wlr,
                             const float* __restrict__ Wlh) {
    int bid = blockIdx.x;
    int ch = bid >> 8, k = bid & 255;
    int n = threadIdx.x;               // 0..127
    const float* Wl = (ch == 0) ? Wlz : (ch == 1) ? Wlr : Wlh;
    float v = (k < 128) ? g_Aw[ch * F * F + k * F + n] : Wl[k * F + n];
    __nv_bfloat16 h = __float2bfloat16(v);
    __nv_bfloat16 l = __float2bfloat16(v - __bfloat162float(h));
    size_t o = (size_t)ch * F * 256 + (size_t)n * 256 + k;
    g_Bh[o] = h;
    g_Bl[o] = l;
}

// ---------------- fp32 GEMM (weight prep only) ----------------
template <int MODE, int NCHUNK>
__global__ void gemm_kernel(const float* __restrict__ A0,
                            const float* __restrict__ A1,
                            const float* __restrict__ B0,
                            const float* __restrict__ B1,
                            float* __restrict__ out, int M) {
    extern __shared__ float sm[];
    float* As = sm;
    float* Bs = sm + BM * ASTR;
    int tid  = threadIdx.x;
    int row0 = blockIdx.x * BM;
    int ty = tid >> 4, tx = tid & 15;
    int r0 = ty * 4, c0 = tx * 8;
    int remRows = M - row0;
    float acc[4][8];
#pragma unroll
    for (int i = 0; i < 4; i++)
#pragma unroll
        for (int j = 0; j < 8; j++) acc[i][j] = 0.f;
#pragma unroll
    for (int kc = 0; kc < NCHUNK; kc++) {
        const float* A  = (kc == 0) ? A0 : A1;
        const float* Bc = (kc == 0) ? B0 : B1;
        const float* Ab = A + (size_t)row0 * F;
        for (int i = tid; i < BM * (F / 4); i += 256) {
            int r  = i >> 5;
            int c4 = i & 31;
            float4 v = make_float4(0.f, 0.f, 0.f, 0.f);
            if (r < remRows) v = ((const float4*)(Ab + (size_t)r * F))[c4];
            *(float4*)(As + r * ASTR + c4 * 4) = v;
        }
        const float4* bsrc = (const float4*)Bc;
#pragma unroll
        for (int i = 0; i < 16; i++)
            ((float4*)Bs)[tid + i * 256] = bsrc[tid + i * 256];
        __syncthreads();
#pragma unroll 8
        for (int k = 0; k < F; k++) {
            float4 bA = *(const float4*)(Bs + k * F + c0);
            float4 bB = *(const float4*)(Bs + k * F + c0 + 4);
            float av[4];
            av[0] = As[(r0 + 0) * ASTR + k];
            av[1] = As[(r0 + 1) * ASTR + k];
            av[2] = As[(r0 + 2) * ASTR + k];
            av[3] = As[(r0 + 3) * ASTR + k];
#pragma unroll
            for (int i = 0; i < 4; i++) {
                acc[i][0] += av[i] * bA.x; acc[i][1] += av[i] * bA.y;
                acc[i][2] += av[i] * bA.z; acc[i][3] += av[i] * bA.w;
                acc[i][4] += av[i] * bB.x; acc[i][5] += av[i] * bB.y;
                acc[i][6] += av[i] * bB.z; acc[i][7] += av[i] * bB.w;
            }
        }
        __syncthreads();
    }
#pragma unroll
    for (int i = 0; i < 4; i++) {
        int gr = row0 + r0 + i;
        if (gr >= M) break;
        size_t base = (size_t)gr * F + c0;
        *(float4*)(out + base)     = make_float4(acc[i][0], acc[i][1], acc[i][2], acc[i][3]);
        *(float4*)(out + base + 4) = make_float4(acc[i][4], acc[i][5], acc[i][6], acc[i][7]);
    }
}

// ---------------- mma.sync split-bf16 GEMM ----------------
// C[M,128] = [A0|A1][M,256] @ B[256,128]; B given as [n][k] hi/lo bf16 images.
// acc = Ah*Bh + Ah*Bl + Al*Bh  (fp32 accumulate)
// MODE 1: out = sigmoid(acc + bias)
// MODE 3: out = H * sigmoid(acc + bias)
// MODE 2: out = Z*H + (1-Z)*tanh(acc + bias)
template <int MODE>
__global__ __launch_bounds__(256, 1)
void tc_gemm(const float* __restrict__ A0, const float* __restrict__ A1,
             const __nv_bfloat16* __restrict__ Bh, const __nv_bfloat16* __restrict__ Bl,
             const float* __restrict__ bias,
             const float* __restrict__ Zb, const float* __restrict__ Hb,
             float* __restrict__ out, int M) {
    extern __shared__ __align__(16) char smem[];
    uint32_t sb = smem_u32(smem);
    int tid = threadIdx.x;
    int wid = tid >> 5, lane = tid & 31;
    int warp_m = wid & 3, warp_n = wid >> 2;      // 4x2 warp grid
    int m0 = warp_m * 32, n0 = warp_n * 64;
    int row0 = blockIdx.x * 128;
    int remRows = M - row0;

    // stage B (hi+lo) into padded smem [128][BSTR]
    {
        const uint4* s0 = (const uint4*)Bh;
        const uint4* s1 = (const uint4*)Bl;
#pragma unroll
        for (int it = 0; it < 16; it++) {
            int idx = tid + it * 256;              // 4096 uint4 total
            int r = idx >> 5, q = idx & 31;        // row n, 16B chunk q
            *(uint4*)(smem + SM_BH + r * (BSTR * 2) + q * 16) = s0[idx];
            *(uint4*)(smem + SM_BL + r * (BSTR * 2) + q * 16) = s1[idx];
        }
    }

    // per-thread ldmatrix source offsets
    int group = lane >> 3, within = lane & 7;
    int a_row = within + ((group == 1 || group == 3) ? 8 : 0);
    int a_col = (group >= 2) ? 8 : 0;
    int b_row = within + ((group >= 2) ? 8 : 0);
    int b_col = (group == 1 || group == 3) ? 8 : 0;
    uint32_t aaddr_h[2], aaddr_l[2], baddr_h[4], baddr_l[4];
#pragma unroll
    for (int i = 0; i < 2; i++) {
        uint32_t off = (uint32_t)((m0 + i * 16 + a_row) * ASTRB + a_col) * 2;
        aaddr_h[i] = sb + SM_AH + off;
        aaddr_l[i] = sb + SM_AL + off;
    }
#pragma unroll
    for (int j = 0; j < 4; j++) {
        uint32_t off = (uint32_t)((n0 + j * 16 + b_row) * BSTR + b_col) * 2;
        baddr_h[j] = sb + SM_BH + off;
        baddr_l[j] = sb + SM_BL + off;
    }

    float acc[2][8][4];
#pragma unroll
    for (int i = 0; i < 2; i++)
#pragma unroll
        for (int j = 0; j < 8; j++)
#pragma unroll
            for (int q = 0; q < 4; q++) acc[i][j][q] = 0.f;

#pragma unroll
    for (int kc = 0; kc < 4; kc++) {
        // convert A chunk (128 rows x 64 cols fp32) -> hi/lo bf16 smem
        const float* Asrc = ((kc < 2) ? A0 : A1) + (size_t)row0 * F + (kc & 1) * 64;
        __syncthreads();   // protect previous chunk's consumers
#pragma unroll
        for (int it = 0; it < 8; it++) {
            int idx = tid + it * 256;              // 2048 float4
            int r = idx >> 4, q = idx & 15;
            float4 v = make_float4(0.f, 0.f, 0.f, 0.f);
            if (r < remRows) v = *(const float4*)(Asrc + (size_t)r * F + q * 4);
            __nv_bfloat16 h0 = __float2bfloat16(v.x), h1 = __float2bfloat16(v.y);
            __nv_bfloat16 h2 = __float2bfloat16(v.z), h3 = __float2bfloat16(v.w);
            uint32_t hi01 = ((uint32_t)__bfloat16_as_ushort(h1) << 16) | __bfloat16_as_ushort(h0);
            uint32_t hi23 = ((uint32_t)__bfloat16_as_ushort(h3) << 16) | __bfloat16_as_ushort(h2);
            uint32_t lo01 = pack_bf2(v.x - __bfloat162float(h0), v.y - __bfloat162float(h1));
            uint32_t lo23 = pack_bf2(v.z - __bfloat162float(h2), v.w - __bfloat162float(h3));
            uint32_t off = (uint32_t)(r * ASTRB + q * 4) * 2;
            *(uint2*)(smem + SM_AH + off) = make_uint2(hi01, hi23);
            *(uint2*)(smem + SM_AL + off) = make_uint2(lo01, lo23);
        }
        __syncthreads();

#pragma unroll
        for (int k16 = 0; k16 < 4; k16++) {
            uint32_t ka = (uint32_t)(k16 * 16) * 2;
            uint32_t kb = (uint32_t)((kc * 64 + k16 * 16)) * 2;
            uint32_t ah[2][4], al[2][4];
#pragma unroll
            for (int i = 0; i < 2; i++) {
                ldm_x4(ah[i], aaddr_h[i] + ka);
                ldm_x4(al[i], aaddr_l[i] + ka);
            }
#pragma unroll
            for (int j = 0; j < 4; j++) {
                uint32_t bh[4], bl[4];
                ldm_x4(bh, baddr_h[j] + kb);
                ldm_x4(bl, baddr_l[j] + kb);
#pragma unroll
                for (int i = 0; i < 2; i++) {
                    mma_bf16(acc[i][2 * j],     ah[i], bh[0], bh[1]);
                    mma_bf16(acc[i][2 * j],     ah[i], bl[0], bl[1]);
                    mma_bf16(acc[i][2 * j],     al[i], bh[0], bh[1]);
                    mma_bf16(acc[i][2 * j + 1], ah[i], bh[2], bh[3]);
                    mma_bf16(acc[i][2 * j + 1], ah[i], bl[2], bl[3]);
                    mma_bf16(acc[i][2 * j + 1], al[i], bh[2], bh[3]);
                }
            }
        }
    }

    // epilogue straight from registers
    int g = lane >> 2, tg = lane & 3;
#pragma unroll
    for (int i = 0; i < 2; i++) {
#pragma unroll
        for (int j = 0; j < 8; j++) {
            int col = n0 + j * 8 + tg * 2;
            float b0 = bias[col], b1 = bias[col + 1];
#pragma unroll
            for (int h = 0; h < 2; h++) {
                int r = row0 + m0 + i * 16 + g + h * 8;
                if (r >= M) continue;
                size_t o = (size_t)r * F + col;
                float v0 = acc[i][j][2 * h]     + b0;
                float v1 = acc[i][j][2 * h + 1] + b1;
                float o0, o1;
                if (MODE == 1) {
                    o0 = 1.f / (1.f + __expf(-v0));
                    o1 = 1.f / (1.f + __expf(-v1));
                } else if (MODE == 3) {
                    o0 = Hb[o]     * (1.f / (1.f + __expf(-v0)));
                    o1 = Hb[o + 1] * (1.f / (1.f + __expf(-v1)));
                } else {
                    float z0 = Zb[o], z1 = Zb[o + 1];
                    o0 = z0 * Hb[o]     + (1.f - z0) * tanhf(v0);
                    o1 = z1 * Hb[o + 1] + (1.f - z1) * tanhf(v1);
                }
                out[o]     = o0;
                out[o + 1] = o1;
            }
        }
    }
}

// ---------------- launch ----------------
extern "C" void kernel_launch(void* const* d_in, const int* in_sizes, int n_in,
                              void* d_out, int out_size) {
    const float* X    = (const float*)d_in[0];
    const int*   eiw  = (const int*)d_in[1];
    const float* ew   = (const float*)d_in[2];
    const float* H    = (const float*)d_in[3];
    const float* W_z  = (const float*)d_in[4];
    const float* b_z  = (const float*)d_in[5];
    const float* W_r  = (const float*)d_in[6];
    const float* b_r  = (const float*)d_in[7];
    const float* W_h  = (const float*)d_in[8];
    const float* b_h  = (const float*)d_in[9];
    const float* Wl_z = (const float*)d_in[10];
    const float* bl_z = (const float*)d_in[11];
    const float* Wl_r = (const float*)d_in[12];
    const float* bl_r = (const float*)d_in[13];
    const float* Wl_h = (const float*)d_in[14];
    const float* bl_h = (const float*)d_in[15];
    float*       out  = (float*)d_out;

    int n = in_sizes[0] / F;   // 50000
    int E = in_sizes[2];       // 800000
    int nf = n * F;

    float *xagg, *Zp, *HRp, *Aw, *cb;
    __nv_bfloat16 *Bh, *Bl;
    cudaGetSymbolAddress((void**)&xagg, g_xagg);
    cudaGetSymbolAddress((void**)&Zp,   g_Z);
    cudaGetSymbolAddress((void**)&HRp,  g_HR);
    cudaGetSymbolAddress((void**)&Aw,   g_Aw);
    cudaGetSymbolAddress((void**)&cb,   g_cb);
    cudaGetSymbolAddress((void**)&Bh,   g_Bh);
    cudaGetSymbolAddress((void**)&Bl,   g_Bl);

    const int smem0 = (BM * ASTR + F * F) * (int)sizeof(float);
    cudaFuncSetAttribute(gemm_kernel<0, 1>, cudaFuncAttributeMaxDynamicSharedMemorySize, smem0);
    cudaFuncSetAttribute(tc_gemm<1>, cudaFuncAttributeMaxDynamicSharedMemorySize, TC_SMEM);
    cudaFuncSetAttribute(tc_gemm<2>, cudaFuncAttributeMaxDynamicSharedMemorySize, TC_SMEM);
    cudaFuncSetAttribute(tc_gemm<3>, cudaFuncAttributeMaxDynamicSharedMemorySize, TC_SMEM);

    probe_kernel<<<1, 256>>>(eiw);
    decode_kernel<<<(E + 255) / 256, 256>>>(eiw, E);
    initdeg_kernel<<<(n + 255) / 256, 256>>>(n);
    deg_kernel<<<(E + 255) / 256, 256>>>(ew, E);
    dinv_kernel<<<(n + 255) / 256, 256>>>(n);
    coef_kernel<<<(E + 255) / 256, 256>>>(ew, E);

    // weight prep
    const int pb = (F + BM - 1) / BM;
    gemm_kernel<0, 1><<<pb, 256, smem0>>>(W_z, nullptr, Wl_z, nullptr, Aw,             F);
    gemm_kernel<0, 1><<<pb, 256, smem0>>>(W_r, nullptr, Wl_r, nullptr, Aw + F * F,     F);
    gemm_kernel<0, 1><<<pb, 256, smem0>>>(W_h, nullptr, Wl_h, nullptr, Aw + 2 * F * F, F);
    biasprep_kernel<<<1, 384>>>(b_z, Wl_z, bl_z, b_r, Wl_r, bl_r, b_h, Wl_h, bl_h);
    bprep_kernel<<<768, 128>>>(Wl_z, Wl_r, Wl_h);

    // graph aggregation of X
    xinit_kernel<<<(nf / 4 + 255) / 256, 256>>>(X, n);
    scatter_kernel<<<(E * 32 + 255) / 256, 256>>>(X, E);

    // tensor-core fused linear stages
    int nb = (n + 127) / 128;
    tc_gemm<1><<<nb, 256, TC_SMEM>>>(xagg, H,   Bh,               Bl,               cb,         nullptr, nullptr, Zp,  n);
    tc_gemm<3><<<nb, 256, TC_SMEM>>>(xagg, H,   Bh + F * 256,     Bl + F * 256,     cb + F,     nullptr, H,       HRp, n);
    tc_gemm<2><<<nb, 256, TC_SMEM>>>(xagg, HRp, Bh + 2 * F * 256, Bl + 2 * F * 256, cb + 2 * F, Zp,      H,       out, n);
}

// round 8
// speedup vs baseline: 3.3307x; 1.1638x over previous
#include <cuda_runtime.h>
#include <cuda_bf16.h>
#include <math.h>
#include <stdint.h>

static constexpr int F    = 128;
static constexpr int NMAX = 50000;
static constexpr int EMAX = 800000;

// ---- tc_gemm smem layout (bytes) ----
static constexpr int SM_BH = 0;
static constexpr int SM_BL = 67584;
static constexpr int SM_AH = 135168;
static constexpr int SM_AL = 153600;
static constexpr int TC_SMEM = 172032;
static constexpr int BSTR = 264;   // bf16 per B smem row (256 + 8 pad)
static constexpr int ASTRB = 72;   // bf16 per A smem row (64 + 8 pad)

// ---------------- scratch ----------------
__device__ float g_xagg[NMAX * F];
__device__ float g_Z   [NMAX * F];
__device__ float g_HR  [NMAX * F];
__device__ float g_cb  [3 * F];
__device__ __nv_bfloat16 g_Bh[3 * F * 256];
__device__ __nv_bfloat16 g_Bl[3 * F * 256];
__device__ float g_deg [NMAX];
__device__ float g_dinv[NMAX];
__device__ int   g_src [EMAX];
__device__ int   g_tgt [EMAX];
__device__ int   g_is64;

// ---------------- helpers ----------------
__device__ __forceinline__ uint32_t smem_u32(const void* p) {
    uint32_t a;
    asm("{ .reg .u64 t; cvta.to.shared.u64 t, %1; cvt.u32.u64 %0, t; }" : "=r"(a) : "l"(p));
    return a;
}
__device__ __forceinline__ void ldm_x4(uint32_t* r, uint32_t addr) {
    asm volatile("ldmatrix.sync.aligned.m8n8.x4.shared.b16 {%0,%1,%2,%3}, [%4];"
                 : "=r"(r[0]), "=r"(r[1]), "=r"(r[2]), "=r"(r[3]) : "r"(addr));
}
__device__ __forceinline__ void mma_bf16(float* c, const uint32_t* a, uint32_t b0, uint32_t b1) {
    asm volatile("mma.sync.aligned.m16n8k16.row.col.f32.bf16.bf16.f32 "
                 "{%0,%1,%2,%3}, {%4,%5,%6,%7}, {%8,%9}, {%0,%1,%2,%3};"
                 : "+f"(c[0]), "+f"(c[1]), "+f"(c[2]), "+f"(c[3])
                 : "r"(a[0]), "r"(a[1]), "r"(a[2]), "r"(a[3]), "r"(b0), "r"(b1));
}
__device__ __forceinline__ uint32_t pack_bf2(float a, float b) {
    __nv_bfloat16 ha = __float2bfloat16(a), hb = __float2bfloat16(b);
    return ((uint32_t)__bfloat16_as_ushort(hb) << 16) | (uint32_t)__bfloat16_as_ushort(ha);
}

// ---------------- epilogue functors ----------------
struct EpiZ {
    float* Zp;
    __device__ __forceinline__ void operator()(size_t o, float v0, float v1) const {
        Zp[o]     = 1.f / (1.f + __expf(-v0));
        Zp[o + 1] = 1.f / (1.f + __expf(-v1));
    }
};
struct EpiHR {
    float* HRp;
    const float* H;
    __device__ __forceinline__ void operator()(size_t o, float v0, float v1) const {
        HRp[o]     = H[o]     * (1.f / (1.f + __expf(-v0)));
        HRp[o + 1] = H[o + 1] * (1.f / (1.f + __expf(-v1)));
    }
};
struct EpiFinal {
    float* out;
    const float* Zb;
    const float* H;
    __device__ __forceinline__ void operator()(size_t o, float v0, float v1) const {
        float z0 = Zb[o], z1 = Zb[o + 1];
        out[o]     = z0 * H[o]     + (1.f - z0) * tanhf(v0);
        out[o + 1] = z1 * H[o + 1] + (1.f - z1) * tanhf(v1);
    }
};

// ---------------- edge-index dtype probe ----------------
__global__ void probe_kernel(const int* __restrict__ w) {
    __shared__ int nz;
    if (threadIdx.x == 0) nz = 0;
    __syncthreads();
    int local = 0;
    for (int i = threadIdx.x; i < 1024; i += blockDim.x)
        if (w[2 * i + 1] != 0) local = 1;
    if (local) atomicOr(&nz, 1);
    __syncthreads();
    if (threadIdx.x == 0) g_is64 = (nz == 0) ? 1 : 0;
}

// decode edge index + accumulate degree in one pass
__global__ void decode_deg_kernel(const int* __restrict__ w,
                                  const float* __restrict__ ew, int E) {
    int e = blockIdx.x * blockDim.x + threadIdx.x;
    if (e >= E) return;
    int s, t;
    if (g_is64) { s = w[2 * e]; t = w[2 * (E + e)]; }
    else        { s = w[e];     t = w[E + e];       }
    g_src[e] = s;
    g_tgt[e] = t;
    atomicAdd(&g_deg[t], ew[e]);
}

__global__ void initdeg_kernel(int n) {
    int i = blockIdx.x * blockDim.x + threadIdx.x;
    if (i < n) g_deg[i] = 1.0f;
}
__global__ void dinv_kernel(int n) {
    int i = blockIdx.x * blockDim.x + threadIdx.x;
    if (i < n) g_dinv[i] = rsqrtf(g_deg[i]);
}
__global__ void xinit_kernel(const float* __restrict__ X, int n) {
    int i4 = blockIdx.x * blockDim.x + threadIdx.x;
    if (i4 >= n * (F / 4)) return;
    int node = i4 >> 5;
    float d = g_dinv[node];
    float d2 = d * d;
    float4 v = ((const float4*)X)[i4];
    ((float4*)g_xagg)[i4] = make_float4(v.x * d2, v.y * d2, v.z * d2, v.w * d2);
}

// one warp per edge; coef computed inline; one v4 gather + one v4 RED per lane
__global__ void scatter_kernel(const float* __restrict__ X,
                               const float* __restrict__ ew, int E) {
    int gw   = (blockIdx.x * blockDim.x + threadIdx.x) >> 5;
    int lane = threadIdx.x & 31;
    if (gw >= E) return;
    int s = g_src[gw];
    int t = g_tgt[gw];
    float c = g_dinv[s] * ew[gw] * g_dinv[t];
    const float4* xp = (const float4*)(X + (size_t)s * F);
    float*        ap = g_xagg + (size_t)t * F + lane * 4;
    float4 v = __ldg(xp + lane);
    asm volatile("red.global.add.v4.f32 [%0], {%1, %2, %3, %4};"
                 :: "l"(ap), "f"(v.x * c), "f"(v.y * c), "f"(v.z * c), "f"(v.w * c)
                 : "memory");
}

__global__ void biasprep_kernel(const float* __restrict__ bz, const float* __restrict__ Wlz, const float* __restrict__ blz,
                                const float* __restrict__ br, const float* __restrict__ Wlr, const float* __restrict__ blr,
                                const float* __restrict__ bh, const float* __restrict__ Wlh, const float* __restrict__ blh) {
    int t = threadIdx.x;               // 384 threads
    int ch = t >> 7, j = t & 127;
    const float* b  = (ch == 0) ? bz  : (ch == 1) ? br  : bh;
    const float* Wl = (ch == 0) ? Wlz : (ch == 1) ? Wlr : Wlh;
    const float* bl = (ch == 0) ? blz : (ch == 1) ? blr : blh;
    float acc = bl[j];
    for (int k = 0; k < F; k++) acc += b[k] * Wl[k * F + j];
    g_cb[ch * F + j] = acc;
}

// B images [ch][n][k]: k<128 -> (W_ch @ Wl_ch_top)[k][n] computed inline; k>=128 -> Wl[k][n].
// grid 768 blocks (ch*256 + k), 128 threads = n
__global__ void bprep_kernel(const float* __restrict__ Wz, const float* __restrict__ Wr, const float* __restrict__ Wh,
                             const float* __restrict__ Wlz, const float* __restrict__ Wlr, const float* __restrict__ Wlh) {
    __shared__ float wrow[128];
    int bid = blockIdx.x;
    int ch = bid >> 8, k = bid & 255;
    int n = threadIdx.x;
    const float* Wl = (ch == 0) ? Wlz : (ch == 1) ? Wlr : Wlh;
    float v;
    if (k < 128) {
        const float* W = (ch == 0) ? Wz : (ch == 1) ? Wr : Wh;
        wrow[n] = W[k * F + n];
        __syncthreads();
        float acc = 0.f;
#pragma unroll 8
        for (int j = 0; j < F; j++) acc += wrow[j] * Wl[j * F + n];
        v = acc;
    } else {
        v = Wl[k * F + n];
    }
    __nv_bfloat16 h = __float2bfloat16(v);
    __nv_bfloat16 l = __float2bfloat16(v - __bfloat162float(h));
    size_t o = (size_t)ch * F * 256 + (size_t)n * 256 + k;
    g_Bh[o] = h;
    g_Bl[o] = l;
}

// ---------------- mma.sync split-bf16 GEMM core ----------------
// acc = [A0|A1][rows, 256] @ B[256,128] with split-bf16 three-product
template <typename EPI>
__device__ __forceinline__
void tc_gemm_body(const float* __restrict__ A0, const float* __restrict__ A1,
                  const __nv_bfloat16* __restrict__ Bh, const __nv_bfloat16* __restrict__ Bl,
                  const float* __restrict__ bias, int row0, int M,
                  char* smem, uint32_t sb, EPI epi) {
    int tid = threadIdx.x;
    int wid = tid >> 5, lane = tid & 31;
    int warp_m = wid & 3, warp_n = wid >> 2;
    int m0 = warp_m * 32, n0 = warp_n * 64;
    int remRows = M - row0;

    // stage B (hi+lo) into padded smem [128][BSTR]
    {
        const uint4* s0 = (const uint4*)Bh;
        const uint4* s1 = (const uint4*)Bl;
#pragma unroll
        for (int it = 0; it < 16; it++) {
            int idx = tid + it * 256;
            int r = idx >> 5, q = idx & 31;
            *(uint4*)(smem + SM_BH + r * (BSTR * 2) + q * 16) = s0[idx];
            *(uint4*)(smem + SM_BL + r * (BSTR * 2) + q * 16) = s1[idx];
        }
    }

    int group = lane >> 3, within = lane & 7;
    int a_row = within + ((group == 1 || group == 3) ? 8 : 0);
    int a_col = (group >= 2) ? 8 : 0;
    int b_row = within + ((group >= 2) ? 8 : 0);
    int b_col = (group == 1 || group == 3) ? 8 : 0;
    uint32_t aaddr_h[2], aaddr_l[2], baddr_h[4], baddr_l[4];
#pragma unroll
    for (int i = 0; i < 2; i++) {
        uint32_t off = (uint32_t)((m0 + i * 16 + a_row) * ASTRB + a_col) * 2;
        aaddr_h[i] = sb + SM_AH + off;
        aaddr_l[i] = sb + SM_AL + off;
    }
#pragma unroll
    for (int j = 0; j < 4; j++) {
        uint32_t off = (uint32_t)((n0 + j * 16 + b_row) * BSTR + b_col) * 2;
        baddr_h[j] = sb + SM_BH + off;
        baddr_l[j] = sb + SM_BL + off;
    }

    float acc[2][8][4];
#pragma unroll
    for (int i = 0; i < 2; i++)
#pragma unroll
        for (int j = 0; j < 8; j++)
#pragma unroll
            for (int q = 0; q < 4; q++) acc[i][j][q] = 0.f;

#pragma unroll
    for (int kc = 0; kc < 4; kc++) {
        const float* Asrc = ((kc < 2) ? A0 : A1) + (size_t)row0 * F + (kc & 1) * 64;
        __syncthreads();
#pragma unroll
        for (int it = 0; it < 8; it++) {
            int idx = tid + it * 256;
            int r = idx >> 4, q = idx & 15;
            float4 v = make_float4(0.f, 0.f, 0.f, 0.f);
            if (r < remRows) v = *(const float4*)(Asrc + (size_t)r * F + q * 4);
            __nv_bfloat16 h0 = __float2bfloat16(v.x), h1 = __float2bfloat16(v.y);
            __nv_bfloat16 h2 = __float2bfloat16(v.z), h3 = __float2bfloat16(v.w);
            uint32_t hi01 = ((uint32_t)__bfloat16_as_ushort(h1) << 16) | __bfloat16_as_ushort(h0);
            uint32_t hi23 = ((uint32_t)__bfloat16_as_ushort(h3) << 16) | __bfloat16_as_ushort(h2);
            uint32_t lo01 = pack_bf2(v.x - __bfloat162float(h0), v.y - __bfloat162float(h1));
            uint32_t lo23 = pack_bf2(v.z - __bfloat162float(h2), v.w - __bfloat162float(h3));
            uint32_t off = (uint32_t)(r * ASTRB + q * 4) * 2;
            *(uint2*)(smem + SM_AH + off) = make_uint2(hi01, hi23);
            *(uint2*)(smem + SM_AL + off) = make_uint2(lo01, lo23);
        }
        __syncthreads();

#pragma unroll
        for (int k16 = 0; k16 < 4; k16++) {
            uint32_t ka = (uint32_t)(k16 * 16) * 2;
            uint32_t kb = (uint32_t)(kc * 64 + k16 * 16) * 2;
            uint32_t ah[2][4], al[2][4];
#pragma unroll
            for (int i = 0; i < 2; i++) {
                ldm_x4(ah[i], aaddr_h[i] + ka);
                ldm_x4(al[i], aaddr_l[i] + ka);
            }
#pragma unroll
            for (int j = 0; j < 4; j++) {
                uint32_t bh[4], bl[4];
                ldm_x4(bh, baddr_h[j] + kb);
                ldm_x4(bl, baddr_l[j] + kb);
#pragma unroll
                for (int i = 0; i < 2; i++) {
                    mma_bf16(acc[i][2 * j],     ah[i], bh[0], bh[1]);
                    mma_bf16(acc[i][2 * j],     ah[i], bl[0], bl[1]);
                    mma_bf16(acc[i][2 * j],     al[i], bh[0], bh[1]);
                    mma_bf16(acc[i][2 * j + 1], ah[i], bh[2], bh[3]);
                    mma_bf16(acc[i][2 * j + 1], ah[i], bl[2], bl[3]);
                    mma_bf16(acc[i][2 * j + 1], al[i], bh[2], bh[3]);
                }
            }
        }
    }

    // epilogue from registers
    int g = lane >> 2, tg = lane & 3;
#pragma unroll
    for (int i = 0; i < 2; i++) {
#pragma unroll
        for (int j = 0; j < 8; j++) {
            int col = n0 + j * 8 + tg * 2;
            float b0 = bias[col], b1 = bias[col + 1];
#pragma unroll
            for (int h = 0; h < 2; h++) {
                int r = row0 + m0 + i * 16 + g + h * 8;
                if (r >= M) continue;
                size_t o = (size_t)r * F + col;
                epi(o, acc[i][j][2 * h] + b0, acc[i][j][2 * h + 1] + b1);
            }
        }
    }
}

// merged Z / HR launch: blockIdx.y selects channel (0 = Z sigmoid, 1 = HR = H*sigmoid)
__global__ __launch_bounds__(256, 1)
void tc_gemm_zr(const float* __restrict__ xagg, const float* __restrict__ H,
                const __nv_bfloat16* __restrict__ Bh, const __nv_bfloat16* __restrict__ Bl,
                const float* __restrict__ cb,
                float* __restrict__ Zp, float* __restrict__ HRp, int M) {
    extern __shared__ __align__(16) char smem[];
    uint32_t sb = smem_u32(smem);
    int y = blockIdx.y;
    int row0 = blockIdx.x * 128;
    const __nv_bfloat16* bh = Bh + (size_t)y * F * 256;
    const __nv_bfloat16* bl = Bl + (size_t)y * F * 256;
    const float* bias = cb + y * F;
    if (y == 0) {
        EpiZ epi{Zp};
        tc_gemm_body(xagg, H, bh, bl, bias, row0, M, smem, sb, epi);
    } else {
        EpiHR epi{HRp, H};
        tc_gemm_body(xagg, H, bh, bl, bias, row0, M, smem, sb, epi);
    }
}

// final: out = Z*H + (1-Z)*tanh(acc + bias)
__global__ __launch_bounds__(256, 1)
void tc_gemm_final(const float* __restrict__ xagg, const float* __restrict__ HR,
                   const __nv_bfloat16* __restrict__ Bh, const __nv_bfloat16* __restrict__ Bl,
                   const float* __restrict__ bias,
                   const float* __restrict__ Zb, const float* __restrict__ H,
                   float* __restrict__ out, int M) {
    extern __shared__ __align__(16) char smem[];
    uint32_t sb = smem_u32(smem);
    int row0 = blockIdx.x * 128;
    EpiFinal epi{out, Zb, H};
    tc_gemm_body(xagg, HR, Bh, Bl, bias, row0, M, smem, sb, epi);
}

// ---------------- launch ----------------
extern "C" void kernel_launch(void* const* d_in, const int* in_sizes, int n_in,
                              void* d_out, int out_size) {
    const float* X    = (const float*)d_in[0];
    const int*   eiw  = (const int*)d_in[1];
    const float* ew   = (const float*)d_in[2];
    const float* H    = (const float*)d_in[3];
    const float* W_z  = (const float*)d_in[4];
    const float* b_z  = (const float*)d_in[5];
    const float* W_r  = (const float*)d_in[6];
    const float* b_r  = (const float*)d_in[7];
    const float* W_h  = (const float*)d_in[8];
    const float* b_h  = (const float*)d_in[9];
    const float* Wl_z = (const float*)d_in[10];
    const float* bl_z = (const float*)d_in[11];
    const float* Wl_r = (const float*)d_in[12];
    const float* bl_r = (const float*)d_in[13];
    const float* Wl_h = (const float*)d_in[14];
    const float* bl_h = (const float*)d_in[15];
    float*       out  = (float*)d_out;

    int n = in_sizes[0] / F;   // 50000
    int E = in_sizes[2];       // 800000
    int nf = n * F;

    float *xagg, *Zp, *HRp, *cb;
    __nv_bfloat16 *Bh, *Bl;
    cudaGetSymbolAddress((void**)&xagg, g_xagg);
    cudaGetSymbolAddress((void**)&Zp,   g_Z);
    cudaGetSymbolAddress((void**)&HRp,  g_HR);
    cudaGetSymbolAddress((void**)&cb,   g_cb);
    cudaGetSymbolAddress((void**)&Bh,   g_Bh);
    cudaGetSymbolAddress((void**)&Bl,   g_Bl);

    cudaFuncSetAttribute(tc_gemm_zr,    cudaFuncAttributeMaxDynamicSharedMemorySize, TC_SMEM);
    cudaFuncSetAttribute(tc_gemm_final, cudaFuncAttributeMaxDynamicSharedMemorySize, TC_SMEM);

    // graph prep
    initdeg_kernel<<<(n + 255) / 256, 256>>>(n);
    probe_kernel<<<1, 256>>>(eiw);
    decode_deg_kernel<<<(E + 255) / 256, 256>>>(eiw, ew, E);
    dinv_kernel<<<(n + 255) / 256, 256>>>(n);

    // weight prep (independent of graph)
    bprep_kernel<<<768, 128>>>(W_z, W_r, W_h, Wl_z, Wl_r, Wl_h);
    biasprep_kernel<<<1, 384>>>(b_z, Wl_z, bl_z, b_r, Wl_r, bl_r, b_h, Wl_h, bl_h);

    // aggregate X
    xinit_kernel<<<(nf / 4 + 255) / 256, 256>>>(X, n);
    scatter_kernel<<<(E * 32 + 255) / 256, 256>>>(X, ew, E);

    // fused linear stages
    int nb = (n + 127) / 128;
    dim3 gzr(nb, 2);
    tc_gemm_zr<<<gzr, 256, TC_SMEM>>>(xagg, H, Bh, Bl, cb, Zp, HRp, n);
    tc_gemm_final<<<nb, 256, TC_SMEM>>>(xagg, HRp, Bh + 2 * F * 256, Bl + 2 * F * 256,
                                        cb + 2 * F, Zp, H, out, n);
}